// round 7
// baseline (speedup 1.0000x reference)
#include <cuda_runtime.h>
#include <cuda_bf16.h>
#include <cstdint>

// ---------------------------------------------------------------------------
// DynamicLoRALinear on GB300 (sm_103 baseline PTX; tcgen05 not available)
//   out = x @ W^T + b + SCALING * ((x @ A[slot]) @ B[slot])
//
//   Base GEMM via 16-bit fixed point on INT8 tensor cores:
//     q = round(v * 32512 / maxabs), split q = X1*256 + X2 (bytes)
//     x@W^T ~= s * (65536*X1W1 + 256*(X1W2 + X2W1)),  s = step_x*step_w
//   mma.sync.m16n8k32.s32.s8 — byte-layout-identical to the proven bf16
//   m16n8k16 pipeline (CTA 128x128, 4 warps 64x64, 3-stage cp.async,
//   SW128 + ldmatrix). 96 K-chunks of 128 s8. Phase-1 acc (X1W1) stashed to
//   global scratch at chunk 31; epilogue combines + bias + 2*h@B[slot].
// ---------------------------------------------------------------------------

#define DINLINE __device__ __forceinline__

static constexpr int BB    = 8;
static constexpr int TT    = 1024;
static constexpr int INF   = 4096;
static constexpr int OUTF  = 4096;
static constexpr int RR    = 16;
static constexpr int M_TOT = BB * TT;          // 8192
static constexpr int KW    = 2 * INF;          // 8192 s8 per row [hi|lo]
static constexpr int NCH   = 96;               // logical chunks of 128 s8
static constexpr float SCALING_F = 2.0f;       // ALPHA/R
static constexpr float QLEV = 32512.0f;        // 127*256 headroom-safe

// ------------------------- scratch (device globals) ------------------------
__device__ __align__(128) int8_t g_xa[(size_t)M_TOT * KW];   // [X1|X2] 64MB
__device__ __align__(128) int8_t g_wb[(size_t)OUTF  * KW];   // [W1|W2] 32MB
__device__ __align__(128) float  g_h[M_TOT * RR];
__device__ __align__(128) int    g_stash[(size_t)2048 * 16384]; // 128MB
__device__ int g_maxx, g_maxw;

// ------------------------------ PTX helpers --------------------------------
DINLINE uint32_t smem_u32(const void* p) {
    uint32_t a;
    asm("{ .reg .u64 t; cvta.to.shared.u64 t, %1; cvt.u32.u64 %0, t; }"
        : "=r"(a) : "l"(p));
    return a;
}

#define SW128(off) ((off) ^ (((off) >> 3) & 0x70))

#define CP_ASYNC16(dst, src) \
    asm volatile("cp.async.cg.shared.global [%0], [%1], 16;" :: "r"(dst), "l"(src) : "memory")
#define CP_COMMIT() asm volatile("cp.async.commit_group;" ::: "memory")
#define CP_WAIT_1() asm volatile("cp.async.wait_group 1;" ::: "memory")
#define CP_WAIT_0() asm volatile("cp.async.wait_group 0;" ::: "memory")

#define LDSM_X4(r0, r1, r2, r3, a) \
    asm volatile("ldmatrix.sync.aligned.m8n8.x4.shared.b16 {%0,%1,%2,%3}, [%4];" \
                 : "=r"(r0), "=r"(r1), "=r"(r2), "=r"(r3) : "r"(a))

DINLINE void mma_s8(int* d, const uint32_t* a, uint32_t b0, uint32_t b1) {
    asm volatile(
        "mma.sync.aligned.m16n8k32.row.col.s32.s8.s8.s32 "
        "{%0,%1,%2,%3}, {%4,%5,%6,%7}, {%8,%9}, {%0,%1,%2,%3};"
        : "+r"(d[0]), "+r"(d[1]), "+r"(d[2]), "+r"(d[3])
        : "r"(a[0]), "r"(a[1]), "r"(a[2]), "r"(a[3]), "r"(b0), "r"(b1));
}

// ---------------------------------------------------------------------------
// K0: zero the absmax accumulators
// ---------------------------------------------------------------------------
__global__ void k_zero2() { g_maxx = 0; g_maxw = 0; }

// ---------------------------------------------------------------------------
// K1: global absmax (float bits of |v| are monotone -> int atomicMax)
// ---------------------------------------------------------------------------
__global__ void __launch_bounds__(256)
k_absmax(const float* __restrict__ in, int total4, int* __restrict__ outbits) {
    const int stride = gridDim.x * blockDim.x;
    float m = 0.f;
    for (int i = blockIdx.x * blockDim.x + threadIdx.x; i < total4; i += stride) {
        float4 v = ((const float4*)in)[i];
        m = fmaxf(m, fmaxf(fmaxf(fabsf(v.x), fabsf(v.y)),
                           fmaxf(fabsf(v.z), fabsf(v.w))));
    }
#pragma unroll
    for (int o = 16; o > 0; o >>= 1)
        m = fmaxf(m, __shfl_xor_sync(0xFFFFFFFFu, m, o));
    if ((threadIdx.x & 31) == 0) atomicMax(outbits, __float_as_int(m));
}

// ---------------------------------------------------------------------------
// K2: quantize fp32 rows of INF -> s8 rows of KW: hi byte at [k], lo at [INF+k]
// ---------------------------------------------------------------------------
__global__ void __launch_bounds__(256)
k_quant(const float* __restrict__ in, int8_t* __restrict__ out,
        const int* __restrict__ maxbits, int total4) {
    const float inv = QLEV / __int_as_float(*maxbits);
    const int stride = gridDim.x * blockDim.x;
    for (int i = blockIdx.x * blockDim.x + threadIdx.x; i < total4; i += stride) {
        const int row = i >> 10, c4 = i & 1023;
        float4 v = ((const float4*)in)[i];
        int q0 = __float2int_rn(v.x * inv);
        int q1 = __float2int_rn(v.y * inv);
        int q2 = __float2int_rn(v.z * inv);
        int q3 = __float2int_rn(v.w * inv);
        int h0 = (q0 + 128) >> 8, h1 = (q1 + 128) >> 8;
        int h2 = (q2 + 128) >> 8, h3 = (q3 + 128) >> 8;
        char4 hi = make_char4((char)h0, (char)h1, (char)h2, (char)h3);
        char4 lo = make_char4((char)(q0 - (h0 << 8)), (char)(q1 - (h1 << 8)),
                              (char)(q2 - (h2 << 8)), (char)(q3 - (h3 << 8)));
        const size_t rb = (size_t)row * KW;
        *(char4*)(out + rb + c4 * 4)       = hi;
        *(char4*)(out + rb + INF + c4 * 4) = lo;
    }
}

// ---------------------------------------------------------------------------
// K3: lora_h[m][r] = sum_k x[m][k] * A[slot(m)][k][r]  (fp32, R6 version)
// ---------------------------------------------------------------------------
__global__ void __launch_bounds__(256)
k_lorah(const float* __restrict__ x, const float* __restrict__ As,
        const int* __restrict__ map, float* __restrict__ h) {
    __shared__ float sA[256 * 16];
    const int tid = threadIdx.x;
    const int m0  = blockIdx.x * 64;
    const int slot = map[m0 / TT];
    const float* Abase = As + (size_t)slot * INF * RR;
    const int tok = tid >> 2;
    const int rq  = tid & 3;
    const float* xrow = x + (size_t)(m0 + tok) * INF;

    float acc0 = 0.f, acc1 = 0.f, acc2 = 0.f, acc3 = 0.f;

    for (int c = 0; c < 16; ++c) {
        __syncthreads();
        const float4* src = (const float4*)(Abase + (size_t)c * 256 * 16);
#pragma unroll
        for (int ii = 0; ii < 4; ++ii)
            ((float4*)sA)[tid + ii * 256] = src[tid + ii * 256];
        __syncthreads();

        const float* xc = xrow + c * 256;
#pragma unroll 4
        for (int j = 0; j < 64; ++j) {
            float4 xv = *(const float4*)(xc + j * 4);
            const float* a0 = sA + (j * 4 + 0) * 16 + rq * 4;
            float4 A0 = *(const float4*)a0;
            float4 A1 = *(const float4*)(a0 + 16);
            float4 A2 = *(const float4*)(a0 + 32);
            float4 A3 = *(const float4*)(a0 + 48);
            acc0 += xv.x * A0.x + xv.y * A1.x + xv.z * A2.x + xv.w * A3.x;
            acc1 += xv.x * A0.y + xv.y * A1.y + xv.z * A2.y + xv.w * A3.y;
            acc2 += xv.x * A0.z + xv.y * A1.z + xv.z * A2.z + xv.w * A3.z;
            acc3 += xv.x * A0.w + xv.y * A1.w + xv.z * A2.w + xv.w * A3.w;
        }
    }

    *(float4*)(h + (size_t)(m0 + tok) * 16 + rq * 4) =
        make_float4(acc0, acc1, acc2, acc3);
}

// ---------------------------------------------------------------------------
// K4: INT8 GEMM + fused epilogue. CTA 128x128, 128 threads, warps 2x2 (64x64).
// Chunk map (128 s8 per chunk):
//   c <  32 : X1 * W1                 (phase 1, scale 65536)
//   32<=c<64: X1 * W2                 (phase 2, scale 256)
//   64<=c<96: X2 * W1                 (phase 2, scale 256)
// ---------------------------------------------------------------------------
static constexpr int TILE_B  = 128 * 128;      // 16KB
static constexpr int STAGE_B = 2 * TILE_B;     // 32KB
static constexpr int STAGES  = 3;
static constexpr uint32_t GEMM_SMEM = STAGES * STAGE_B + 1024;
static constexpr int ROWSTRIDE_B = KW;         // 8192 bytes per gmem row

DINLINE void kmap(int c, int& a, int& b) {
    if (c < 32)      { a = c * 128;            b = c * 128; }
    else if (c < 64) { a = (c - 32) * 128;     b = INF + (c - 32) * 128; }
    else             { a = INF + (c - 64) * 128; b = (c - 64) * 128; }
}

__global__ void __launch_bounds__(128, 2)
k_gemm(const int8_t* __restrict__ Abuf,
       const int8_t* __restrict__ Bbuf,
       const float* __restrict__ bias,
       const float* __restrict__ Bs,
       const int* __restrict__ map,
       const float* __restrict__ h,
       float* __restrict__ out) {
    extern __shared__ char smraw[];
    const uint32_t raw  = smem_u32(smraw);
    const uint32_t base = (raw + 1023u) & ~1023u;
    char* p_base = smraw + (base - raw);
    const int tid = threadIdx.x, wid = tid >> 5, lane = tid & 31;
    const int wm = wid >> 1, wn = wid & 1;
    const int m0 = blockIdx.y * 128, n0 = blockIdx.x * 128;
    const size_t ctaId = (size_t)(blockIdx.y * gridDim.x + blockIdx.x);

    const char* gAt = (const char*)(Abuf + (size_t)m0 * KW)
                      + (size_t)(tid >> 3) * ROWSTRIDE_B + (tid & 7) * 16;
    const char* gBt = (const char*)(Bbuf + (size_t)n0 * KW)
                      + (size_t)(tid >> 3) * ROWSTRIDE_B + (tid & 7) * 16;
    uint32_t offs[8];
#pragma unroll
    for (int ii = 0; ii < 8; ++ii)
        offs[ii] = SW128((uint32_t)((((tid >> 3) + 16 * ii) * 128) + (tid & 7) * 16));

    auto load_full = [&](int s, int c) {
        const uint32_t sb = base + s * STAGE_B;
        int kbA, kbB; kmap(c, kbA, kbB);
#pragma unroll
        for (int ii = 0; ii < 8; ++ii)
            CP_ASYNC16(sb + offs[ii], gAt + (size_t)ii * (16 * ROWSTRIDE_B) + kbA);
#pragma unroll
        for (int ii = 0; ii < 8; ++ii)
            CP_ASYNC16(sb + TILE_B + offs[ii], gBt + (size_t)ii * (16 * ROWSTRIDE_B) + kbB);
        CP_COMMIT();
    };

    load_full(0, 0);
    load_full(1, 1);

    int acc[4][8][4];
#pragma unroll
    for (int a = 0; a < 4; ++a)
#pragma unroll
        for (int b = 0; b < 8; ++b)
#pragma unroll
            for (int c = 0; c < 4; ++c) acc[a][b][c] = 0;

    const int lrow = lane & 15;
    const uint32_t lkh = (uint32_t)((lane >> 4) << 4);

    for (int i = 0; i < NCH; ++i) {
        if (i == NCH - 1) { CP_WAIT_0(); } else { CP_WAIT_1(); }
        __syncthreads();
        const bool doload = (i + 2 < NCH);
        const uint32_t sld = base + ((i + 2) % STAGES) * STAGE_B;
        int kbA = 0, kbB = 0;
        if (doload) kmap(i + 2, kbA, kbB);
        const uint32_t sA = base + (i % STAGES) * STAGE_B;
        const uint32_t sB = sA + TILE_B;
#pragma unroll
        for (int ks = 0; ks < 4; ++ks) {
            if (doload) {   // 4 of the 16 next-stage loads per ks
                const int i0 = 2 * ks, i1 = 2 * ks + 1;
                CP_ASYNC16(sld + offs[i0],
                           gAt + (size_t)i0 * (16 * ROWSTRIDE_B) + kbA);
                CP_ASYNC16(sld + offs[i1],
                           gAt + (size_t)i1 * (16 * ROWSTRIDE_B) + kbA);
                CP_ASYNC16(sld + TILE_B + offs[i0],
                           gBt + (size_t)i0 * (16 * ROWSTRIDE_B) + kbB);
                CP_ASYNC16(sld + TILE_B + offs[i1],
                           gBt + (size_t)i1 * (16 * ROWSTRIDE_B) + kbB);
            }
            const uint32_t kc = (uint32_t)(ks * 32) + lkh;
            uint32_t ar[4][4], br[4][4];
#pragma unroll
            for (int t = 0; t < 4; ++t) {
                uint32_t a = sA + SW128((uint32_t)((wm * 64 + t * 16 + lrow) * 128) + kc);
                LDSM_X4(ar[t][0], ar[t][1], ar[t][2], ar[t][3], a);
            }
#pragma unroll
            for (int t = 0; t < 4; ++t) {
                uint32_t a = sB + SW128((uint32_t)((wn * 64 + t * 16 + lrow) * 128) + kc);
                LDSM_X4(br[t][0], br[t][1], br[t][2], br[t][3], a);
            }
#pragma unroll
            for (int tm = 0; tm < 4; ++tm)
#pragma unroll
                for (int tn = 0; tn < 8; ++tn)
                    mma_s8(acc[tm][tn], ar[tm],
                           br[tn >> 1][tn & 1], br[tn >> 1][2 + (tn & 1)]);
        }
        if (doload) CP_COMMIT();
        if (i == 31) {   // end of phase 1: stash X1W1 acc, restart at zero
            int* af = &acc[0][0][0];
            int* st = g_stash + ctaId * 16384 + tid;
#pragma unroll
            for (int j = 0; j < 128; ++j) st[(size_t)j * 128] = af[j];
#pragma unroll
            for (int j = 0; j < 128; ++j) af[j] = 0;
        }
    }

    // --- fused epilogue: out = s*(65536*acc1 + 256*acc2) + bias + 2*h@B -----
    float* sH    = (float*)p_base;        // 128 x 16  (8KB)
    float* sBm   = sH + 2048;             // 16 x 128  (8KB)
    float* sbias = sBm + 2048;            // 128       (512B)
    const int slot = map[m0 >> 10];
    {
        const float4* hs = (const float4*)(h + (size_t)m0 * 16);
#pragma unroll
        for (int q = tid; q < 512; q += 128) ((float4*)sH)[q] = hs[q];
        const float* Bbase = Bs + (size_t)slot * RR * OUTF + n0;
#pragma unroll
        for (int q = tid; q < 512; q += 128) {
            int r = q >> 5, c4 = q & 31;
            ((float4*)sBm)[q] = *(const float4*)(Bbase + (size_t)r * OUTF + c4 * 4);
        }
        if (tid < 32) ((float4*)sbias)[tid] = ((const float4*)(bias + n0))[tid];
    }
    __syncthreads();

    const float stepx = __int_as_float(g_maxx) / QLEV;
    const float stepw = __int_as_float(g_maxw) / QLEV;
    const float sxw = stepx * stepw;
    const int* st = g_stash + ctaId * 16384 + tid;

    const int erow = lane >> 2, ecol = (lane & 3) * 2;
#pragma unroll
    for (int tm = 0; tm < 4; ++tm) {
        const int r0 = wm * 64 + tm * 16 + erow;
        float h0[16], h1[16];
#pragma unroll
        for (int r = 0; r < 16; ++r) { h0[r] = sH[r0 * 16 + r]; h1[r] = sH[(r0 + 8) * 16 + r]; }
#pragma unroll
        for (int tn = 0; tn < 8; ++tn) {
            const int nl = wn * 64 + tn * 8 + ecol;
            float d00 = 0.f, d01 = 0.f, d10 = 0.f, d11 = 0.f;
#pragma unroll
            for (int r = 0; r < 16; ++r) {
                float B0 = sBm[r * 128 + nl], B1 = sBm[r * 128 + nl + 1];
                d00 += h0[r] * B0; d01 += h0[r] * B1;
                d10 += h1[r] * B0; d11 += h1[r] * B1;
            }
            const float b0 = sbias[nl], b1 = sbias[nl + 1];
            const int jb = tm * 32 + tn * 4;
            float g00 = sxw * (65536.f * (float)st[(size_t)(jb + 0) * 128]
                               + 256.f * (float)acc[tm][tn][0]);
            float g01 = sxw * (65536.f * (float)st[(size_t)(jb + 1) * 128]
                               + 256.f * (float)acc[tm][tn][1]);
            float g10 = sxw * (65536.f * (float)st[(size_t)(jb + 2) * 128]
                               + 256.f * (float)acc[tm][tn][2]);
            float g11 = sxw * (65536.f * (float)st[(size_t)(jb + 3) * 128]
                               + 256.f * (float)acc[tm][tn][3]);
            float* p = out + (size_t)(m0 + r0) * OUTF + n0 + nl;
            *(float2*)p = make_float2(g00 + b0 + SCALING_F * d00,
                                      g01 + b1 + SCALING_F * d01);
            *(float2*)(p + (size_t)8 * OUTF) =
                make_float2(g10 + b0 + SCALING_F * d10,
                            g11 + b1 + SCALING_F * d11);
        }
    }
}

// ---------------------------------------------------------------------------
extern "C" void kernel_launch(void* const* d_in, const int* in_sizes, int n_in,
                              void* d_out, int out_size) {
    const float* x    = (const float*)d_in[0];
    const int*   map  = (const int*)d_in[1];
    const float* W    = (const float*)d_in[2];
    const float* bias = (const float*)d_in[3];
    const float* As   = (const float*)d_in[4];
    const float* Bs   = (const float*)d_in[5];
    float* out = (float*)d_out;

    int8_t *xa, *wb;
    float* hbuf;
    int *maxx, *maxw;
    cudaGetSymbolAddress((void**)&xa, g_xa);
    cudaGetSymbolAddress((void**)&wb, g_wb);
    cudaGetSymbolAddress((void**)&hbuf, g_h);
    cudaGetSymbolAddress((void**)&maxx, g_maxx);
    cudaGetSymbolAddress((void**)&maxw, g_maxw);

    cudaFuncSetAttribute(k_gemm, cudaFuncAttributeMaxDynamicSharedMemorySize,
                         (int)GEMM_SMEM);

    k_zero2<<<1, 1>>>();
    k_absmax<<<1024, 256>>>(x, M_TOT * (INF / 4), maxx);
    k_absmax<<<512, 256>>>(W, OUTF * (INF / 4), maxw);
    k_quant<<<1024, 256>>>(x, xa, maxx, M_TOT * (INF / 4));
    k_quant<<<512, 256>>>(W, wb, maxw, OUTF * (INF / 4));
    k_lorah<<<M_TOT / 64, 256>>>(x, As, map, hbuf);
    k_gemm<<<dim3(OUTF / 128, M_TOT / 128), 128, GEMM_SMEM>>>(
        xa, wb, bias, Bs, map, hbuf, out);
}